// round 15
// baseline (speedup 1.0000x reference)
#include <cuda_runtime.h>
#include <cuda_fp16.h>
#include <cstdint>

// ---------------------------------------------------------------------------
// AnalogConv2d: 3x3 s1 p1, N=16 C=128 H=W=56 Cout=256, fp32 + bias.
// fp16 mma.sync.m16n8k16 (fp32 accum) implicit GEMM.
// R14: TM=128 x TN=128 CTA, 512 threads, 16 warps (4Mx4N), warp tile 32x32,
// acc=32 regs, <=64 regs (__launch_bounds__(512,2)), 3-stage x 32KB smem
// -> TWO CTAs per SM = 8 warps/SMSP (double R12). Tests the eligible-warp
// starvation theory: R12 (4 w/SMSP) beat 2-w/SMSP configs despite more L1.
// K = 9 taps * 128 ch, chunk 64 (NCHUNK=18).
// ---------------------------------------------------------------------------

#define CIN    128
#define HWD    56
#define LSP    3136
#define COUT   256
#define NIMG   16
#define LTOT   (NIMG * LSP)        // 50176
#define X4N    (NIMG * 16 * LSP)   // 802816 uint4 granules (8 ch each)
#define WT_N   (9 * 2 * 2 * 8 * 4 * 32 * 4)   // 147456
#define TM     128
#define TN     128
#define NCTA_X (LTOT / TN)         // 392
#define NCHUNK 18                  // 9 taps * 2 (CHK=64 channels)
#define STAGES 3
#define A_ST_B 16384u              // 128*64*2
#define B_ST_B 16384u              // 128*64*2
#define STG_B  (A_ST_B + B_ST_B)   // 32768
#define SMEMB  (STAGES * STG_B)    // 98304 (96KB) -> 2 CTAs/SM

// Weights fragment-major fp16 pairs: [tap][half2][ck2][mf8][ks4][lane32][4]
__device__ __align__(256) uint32_t g_Wh[WT_N];
// x packed 8-channel fp16 granules: [img][c8(16)][l(3136)], one uint4 each
__device__ __align__(256) uint4 g_X4[X4N];

__device__ __forceinline__ void cpa16(uint32_t d, const void* s) {
    asm volatile("cp.async.cg.shared.global [%0], [%1], 16;" :: "r"(d), "l"(s));
}
__device__ __forceinline__ void cpa16z(uint32_t d, const void* s, uint32_t sz) {
    asm volatile("cp.async.cg.shared.global [%0], [%1], 16, %2;"
                 :: "r"(d), "l"(s), "r"(sz));
}
__device__ __forceinline__ void mma_f16(float* d, const uint32_t* a,
                                        const uint32_t* b) {
    asm volatile(
        "mma.sync.aligned.m16n8k16.row.col.f32.f16.f16.f32 "
        "{%0,%1,%2,%3}, {%4,%5,%6,%7}, {%8,%9}, {%0,%1,%2,%3};"
        : "+f"(d[0]), "+f"(d[1]), "+f"(d[2]), "+f"(d[3])
        : "r"(a[0]), "r"(a[1]), "r"(a[2]), "r"(a[3]), "r"(b[0]), "r"(b[1]));
}
__device__ __forceinline__ void ldmx4(uint32_t& r0, uint32_t& r1,
                                      uint32_t& r2, uint32_t& r3, uint32_t a) {
    asm volatile("ldmatrix.sync.aligned.m8n8.x4.shared.b16 {%0,%1,%2,%3}, [%4];"
                 : "=r"(r0), "=r"(r1), "=r"(r2), "=r"(r3) : "r"(a));
}

// ---------------------------------------------------------------------------
// Fused transform: x -> g_X4 (8ch granules), w -> g_Wh fragment-major.
// g_Wh idx = ((((((tap*2+half)*2+ck)*8+mf)*4+ks)*32+lane)*4 + r
// m16n8k16 A frag: r0:(g,2tig) r1:(g+8,2tig) r2:(g,2tig+8) r3:(g+8,2tig+8)
// ---------------------------------------------------------------------------
__global__ void transform_kernel(const float* __restrict__ x,
                                 const float* __restrict__ w) {
    int i = blockIdx.x * blockDim.x + threadIdx.x;
    if (i < X4N) {
        int l  = i % LSP;
        int t  = i / LSP;
        int c8 = t & 15;
        int im = t >> 4;
        const float* p = x + ((size_t)im * CIN + c8 * 8) * LSP + l;
        uint32_t wds[4];
        #pragma unroll
        for (int j = 0; j < 4; ++j) {
            __half2 h = __floats2half2_rn(p[(size_t)(2 * j) * LSP],
                                          p[(size_t)(2 * j + 1) * LSP]);
            wds[j] = *reinterpret_cast<uint32_t*>(&h);
        }
        uint4 v = { wds[0], wds[1], wds[2], wds[3] };
        g_X4[i] = v;
    } else {
        int idx = i - X4N;
        if (idx >= WT_N) return;
        int r    = idx & 3;
        int lane = (idx >> 2) & 31;
        int ks   = (idx >> 7) & 3;
        int mf   = (idx >> 9) & 7;
        int ck   = (idx >> 12) & 1;
        int half = (idx >> 13) & 1;
        int tap  = idx >> 14;
        int g = lane >> 2, tig = lane & 3;
        int co = half * 128 + mf * 16 + g + 8 * (r & 1);
        int c  = ck * 64 + ks * 16 + 2 * tig + 8 * (r >> 1);
        __half2 v = __floats2half2_rn(w[(co * CIN + c) * 9 + tap],
                                      w[(co * CIN + c + 1) * 9 + tap]);
        g_Wh[idx] = *reinterpret_cast<uint32_t*>(&v);
    }
}

// ---------------------------------------------------------------------------
__global__ void __launch_bounds__(512, 2)
conv_mma_kernel(const float* __restrict__ bias,
                float* __restrict__ out) {
    extern __shared__ float smem[];
    uint32_t sb;
    asm("{ .reg .u64 t; cvta.to.shared.u64 t, %1; cvt.u32.u64 %0, t; }"
        : "=r"(sb) : "l"(smem));

    const int tid  = threadIdx.x;
    const int wid  = tid >> 5;
    const int lane = tid & 31;
    const int wm   = wid >> 2;        // 0..3 : 32-row Cout band
    const int wn   = wid & 3;         // 0..3 : 32-col pos band

    const int half = blockIdx.y;      // Cout half
    const int l0   = blockIdx.x * TN;

    // ---- B gather setup: thread -> (pos, jb); 2 x 16B granules each ----
    const int pos = tid & 127;
    const int jb  = (tid >> 7) * 2;    // granule base within chunk: 0,2,4,6
    const int l   = l0 + pos;
    const int img = l / LSP;
    const int rl  = l - img * LSP;
    const int oh  = rl / HWD;
    const int ow  = rl - oh * HWD;
    const uint4* xb = g_X4 + (size_t)img * 16 * LSP;
    const uint32_t hsw3 = (uint32_t)pos & 7u;
    const uint32_t bdst_row = (uint32_t)pos * 32u;   // words per B row

    // ---- ldmatrix lane address precompute ----
    const int lt = lane >> 3;          // tile 0..3 within one ldmx4
    const int lr = lane & 7;           // row within m8 tile
    const int lh = lt & 1;             // k-half
    const uint32_t lanebase =
        (uint32_t)(wn * 32 + (lt >> 1) * 8 + lr) * 128u;   // bytes

    float acc[2][4][4];
    #pragma unroll
    for (int mi = 0; mi < 2; ++mi)
        #pragma unroll
        for (int ni = 0; ni < 4; ++ni)
            #pragma unroll
            for (int r2 = 0; r2 < 4; ++r2)
                acc[mi][ni][r2] = 0.0f;

    auto prefetch = [&](int q, int s) {
        const int tap = q >> 1;
        const int ck  = q & 1;
        const int ki  = tap / 3, kj = tap - ki * 3;
        const uint32_t sbase = sb + (uint32_t)s * STG_B;
        // A: 16KB contiguous fragment-major, 2 x 16B per thread
        const uint32_t* asrc =
            g_Wh + (((size_t)((tap * 2 + half) * 2 + ck)) << 12);
        #pragma unroll
        for (int i = 0; i < 2; ++i)
            cpa16(sbase + (uint32_t)(i * 512 + tid) * 16u,
                  asrc + (i * 512 + tid) * 4);
        // B: 2 x 16B granules (8 channels each), coalesced across pos
        const int ih = oh + ki - 1, iw = ow + kj - 1;
        const bool valid = ((unsigned)ih < HWD) & ((unsigned)iw < HWD);
        const uint4* src = valid
            ? (xb + (size_t)(ck * 8 + jb) * LSP + ih * HWD + iw)
            : g_X4;
        const uint32_t sz = valid ? 16u : 0u;
        const uint32_t bb = sbase + A_ST_B;
        #pragma unroll
        for (int i = 0; i < 2; ++i) {
            uint32_t gi = (uint32_t)(jb + i);
            cpa16z(bb + (bdst_row + ((gi ^ hsw3) << 2)) * 4u,
                   src + (size_t)i * LSP, sz);
        }
    };

    auto compute = [&](int s) {
        const uint4* A4 = (const uint4*)(smem + s * (STG_B / 4));
        const uint32_t bB = sb + (uint32_t)s * STG_B + A_ST_B + lanebase;

        #pragma unroll
        for (int ks = 0; ks < 4; ++ks) {
            // B fragments for this ks: 2 x ldmx4 covers ni 0..3
            uint32_t bf[4][2];
            const uint32_t goff = (uint32_t)(((2 * ks + lh) ^ lr) << 4);
            #pragma unroll
            for (int p = 0; p < 2; ++p)
                ldmx4(bf[p * 2][0], bf[p * 2][1],
                      bf[p * 2 + 1][0], bf[p * 2 + 1][1],
                      bB + (uint32_t)p * 2048u + goff);
            // A fragments: mf = wm*2 + mi
            #pragma unroll
            for (int mi = 0; mi < 2; ++mi) {
                uint4 af = A4[((wm * 2 + mi) * 4 + ks) * 32 + lane];
                uint32_t a_[4] = { af.x, af.y, af.z, af.w };
                #pragma unroll
                for (int ni = 0; ni < 4; ++ni)
                    mma_f16(acc[mi][ni], a_, bf[ni]);
            }
        }
    };

    // ---- 3-stage pipeline, one sync per chunk ----
    #pragma unroll
    for (int s = 0; s < STAGES - 1; ++s) {
        prefetch(s, s);
        asm volatile("cp.async.commit_group;" ::: "memory");
    }
    int sidx = STAGES - 1;
    int cidx = 0;
    #pragma unroll 1
    for (int q = 0; q < NCHUNK; ++q) {
        asm volatile("cp.async.wait_group %0;" :: "n"(STAGES - 2) : "memory");
        __syncthreads();
        if (q + STAGES - 1 < NCHUNK)
            prefetch(q + STAGES - 1, sidx);
        asm volatile("cp.async.commit_group;" ::: "memory");
        compute(cidx);
        sidx = (sidx == STAGES - 1) ? 0 : sidx + 1;
        cidx = (cidx == STAGES - 1) ? 0 : cidx + 1;
    }

    // ---- epilogue: +bias, float2 stores ----
    const int g   = lane >> 2;
    const int tig = lane & 3;
    const int co_base = half * 128 + wm * 32 + g;
    float bv[2][2];
    #pragma unroll
    for (int mi = 0; mi < 2; ++mi) {
        bv[mi][0] = bias[co_base + mi * 16];
        bv[mi][1] = bias[co_base + mi * 16 + 8];
    }
    #pragma unroll
    for (int ni = 0; ni < 4; ++ni) {
        const int le  = l0 + wn * 32 + ni * 8 + 2 * tig;
        const int im2 = le / LSP;
        const int rle = le - im2 * LSP;
        float* ob = out + (size_t)im2 * COUT * LSP + rle;
        #pragma unroll
        for (int mi = 0; mi < 2; ++mi) {
            #pragma unroll
            for (int h = 0; h < 2; ++h) {
                const int co = co_base + mi * 16 + h * 8;
                float2 v;
                v.x = acc[mi][ni][h * 2 + 0] + bv[mi][h];
                v.y = acc[mi][ni][h * 2 + 1] + bv[mi][h];
                *reinterpret_cast<float2*>(ob + (size_t)co * LSP) = v;
            }
        }
    }
}

// ---------------------------------------------------------------------------
extern "C" void kernel_launch(void* const* d_in, const int* in_sizes, int n_in,
                              void* d_out, int out_size) {
    const float* x    = (const float*)d_in[0];
    const float* w    = (const float*)d_in[1];
    const float* bias = (const float*)d_in[2];
    float* out = (float*)d_out;

    cudaFuncSetAttribute(conv_mma_kernel,
                         cudaFuncAttributeMaxDynamicSharedMemorySize, SMEMB);

    transform_kernel<<<(X4N + WT_N + 255) / 256, 256>>>(x, w);
    dim3 grid(NCTA_X, 2, 1);
    conv_mma_kernel<<<grid, 512, SMEMB>>>(bias, out);
}

// round 16
// speedup vs baseline: 1.1078x; 1.1078x over previous
#include <cuda_runtime.h>
#include <cuda_fp16.h>
#include <cstdint>

// ---------------------------------------------------------------------------
// AnalogConv2d: 3x3 s1 p1, N=16 C=128 H=W=56 Cout=256, fp32 + bias.
// fp16 mma.sync.m16n8k16 (fp32 accum) implicit GEMM.
// R15 = R12 core (256x128 CTA, 512 thr, 16 warps 4Mx4N, warp 64x32,
// 4-stage A pipeline, CHK=64) + structural B overhaul:
//  - x stored ZERO-PADDED per image (58x58) in 8-channel 16B granules
//  - K loop reordered (ck outer, tap inner): ONE haloed B slab (246 rows)
//    per ck serves all 9 taps; taps = ldmatrix at row+shift (swizzle keys
//    on absolute row -> conflict-free for every shift)
//  - B STS+fill 576KB -> 128KB per CTA; no divmod/branches in gather
//  - tiles over padded rows: 26 tiles/img, 416 CTAs (wave 1.13 -> 1.07);
//    pad-column outputs discarded by predicated scalar epilogue
// ---------------------------------------------------------------------------

#define CIN    128
#define HWD    56
#define HP     58            // padded width/height
#define PAREA  3364          // 58*58
#define PIMG3  3584          // per (img,c8) slab stride (slack zeroed)
#define POFF   64            // image start offset inside slab
#define LSP    3136
#define COUT   256
#define NIMG   16
#define TPI    26            // tiles per image (26*128 = 3328 >= 56*58)
#define NCTA   (NIMG * TPI)  // 416
#define X4PN   (NIMG * 16 * PIMG3)          // 917504 pack threads
#define WT_N   (18 * 8192)                  // 147456 weight words
#define NCHUNK 18            // q = ck*9 + tap
#define A_STG  32768u
#define B_STG  32768u        // 256 rows x 128B (246 used)
#define B_OFF  (4u * A_STG)  // 131072
#define SMEMB  (4u * A_STG + 2u * B_STG)    // 196608 (192KB)

// Weights fragment-major fp16 pairs, contiguous per q-segment:
// g_Wh[(q<<13) + [mf16][ks4][lane32][4]],  q = ck*9 + tap
__device__ __align__(256) uint32_t g_Wh[WT_N];
// x padded, 8-channel granules: [img][c8(16)][PIMG3], zero borders + slack
__device__ __align__(256) uint4 g_X4p[NIMG * 16 * PIMG3];

__device__ __forceinline__ void cpa16(uint32_t d, const void* s) {
    asm volatile("cp.async.cg.shared.global [%0], [%1], 16;" :: "r"(d), "l"(s));
}
__device__ __forceinline__ void mma_f16(float* d, const uint32_t* a,
                                        const uint32_t* b) {
    asm volatile(
        "mma.sync.aligned.m16n8k16.row.col.f32.f16.f16.f32 "
        "{%0,%1,%2,%3}, {%4,%5,%6,%7}, {%8,%9}, {%0,%1,%2,%3};"
        : "+f"(d[0]), "+f"(d[1]), "+f"(d[2]), "+f"(d[3])
        : "r"(a[0]), "r"(a[1]), "r"(a[2]), "r"(a[3]), "r"(b[0]), "r"(b[1]));
}
__device__ __forceinline__ void ldmx4(uint32_t& r0, uint32_t& r1,
                                      uint32_t& r2, uint32_t& r3, uint32_t a) {
    asm volatile("ldmatrix.sync.aligned.m8n8.x4.shared.b16 {%0,%1,%2,%3}, [%4];"
                 : "=r"(r0), "=r"(r1), "=r"(r2), "=r"(r3) : "r"(a));
}

// ---------------------------------------------------------------------------
// Fused transform: x -> g_X4p (padded, zeroed), w -> g_Wh (q-segment layout)
// ---------------------------------------------------------------------------
__global__ void transform_kernel(const float* __restrict__ x,
                                 const float* __restrict__ w) {
    int i = blockIdx.x * blockDim.x + threadIdx.x;
    if (i < X4PN) {
        int pslot = i % PIMG3;
        int t  = i / PIMG3;
        int c8 = t & 15;
        int im = t >> 4;
        uint4 v = { 0u, 0u, 0u, 0u };
        int p = pslot - POFF;
        if (p >= 0 && p < PAREA) {
            int row = p / HP;
            int col = p - row * HP;
            if (row >= 1 && row <= 56 && col >= 1 && col <= 56) {
                const float* s = x + ((size_t)im * CIN + c8 * 8) * LSP
                               + (row - 1) * HWD + (col - 1);
                uint32_t wd[4];
                #pragma unroll
                for (int j = 0; j < 4; ++j) {
                    __half2 h = __floats2half2_rn(s[(size_t)(2 * j) * LSP],
                                                  s[(size_t)(2 * j + 1) * LSP]);
                    wd[j] = *reinterpret_cast<uint32_t*>(&h);
                }
                v.x = wd[0]; v.y = wd[1]; v.z = wd[2]; v.w = wd[3];
            }
        }
        g_X4p[i] = v;
    } else {
        int idx = i - X4PN;
        if (idx >= WT_N) return;
        int inner = idx & 8191;
        int seg   = idx >> 13;           // q = ck*9 + tap
        int ck    = (seg >= 9) ? 1 : 0;
        int tap   = seg - ck * 9;
        int r    = inner & 3;
        int lane = (inner >> 2) & 31;
        int ks   = (inner >> 7) & 3;
        int mf   = (inner >> 9) & 15;
        int g = lane >> 2, tig = lane & 3;
        int co = mf * 16 + g + 8 * (r & 1);
        int c  = ck * 64 + ks * 16 + 2 * tig + 8 * (r >> 1);
        __half2 v = __floats2half2_rn(w[(co * CIN + c) * 9 + tap],
                                      w[(co * CIN + c + 1) * 9 + tap]);
        g_Wh[idx] = *reinterpret_cast<uint32_t*>(&v);
    }
}

// ---------------------------------------------------------------------------
__global__ void __launch_bounds__(512, 1)
conv_mma_kernel(const float* __restrict__ bias,
                float* __restrict__ out) {
    extern __shared__ float smem[];
    uint32_t sb;
    asm("{ .reg .u64 t; cvta.to.shared.u64 t, %1; cvt.u32.u64 %0, t; }"
        : "=r"(sb) : "l"(smem));

    const int tid  = threadIdx.x;
    const int wid  = tid >> 5;
    const int lane = tid & 31;
    const int wm   = wid >> 2;        // 0..3 : 64-row Cout band
    const int wn   = wid & 3;         // 0..3 : 32-col pos band

    const int bx  = blockIdx.x;
    const int img = bx / TPI;
    const int tq  = bx - img * TPI;
    const int p0  = HP + tq * 128;    // padded position base (row >= 1)

    // ---- B halo loader: 2048 granule-slots, 4 per thread, coalesced ----
    const size_t xslab = (size_t)img * 16;
    auto loadB = [&](int ck, int bsel) {
        const uint32_t bb = sb + B_OFF + (uint32_t)bsel * B_STG;
        #pragma unroll
        for (int i = 0; i < 4; ++i) {
            int idx = i * 512 + tid;
            int r  = idx & 255;       // halo row (246 used; slop reads safe)
            int gi = idx >> 8;        // granule (channel octet) 0..7
            const uint4* src = g_X4p + (xslab + ck * 8 + gi) * PIMG3
                             + (POFF + p0 - 59 + r);
            cpa16(bb + (uint32_t)(r * 128) + ((uint32_t)(gi ^ (r & 7)) << 4),
                  src);
        }
    };
    auto prefetchA = [&](int q, int s) {
        const uint32_t* asrc = g_Wh + ((size_t)q << 13);
        const uint32_t sbase = sb + (uint32_t)s * A_STG;
        #pragma unroll
        for (int i = 0; i < 4; ++i)
            cpa16(sbase + (uint32_t)(i * 512 + tid) * 16u,
                  asrc + (i * 512 + tid) * 4);
    };

    // ---- ldmatrix row constants (absolute-row swizzle) ----
    const int lt = lane >> 3;
    const int lr = lane & 7;
    const int lh = lt & 1;
    const int rowc = wn * 32 + ((lt >> 1) << 3) + lr + 59;

    float acc[4][4][4];
    #pragma unroll
    for (int mi = 0; mi < 4; ++mi)
        #pragma unroll
        for (int ni = 0; ni < 4; ++ni)
            #pragma unroll
            for (int r2 = 0; r2 < 4; ++r2)
                acc[mi][ni][r2] = 0.0f;

    auto compute = [&](int s, int shift, int bsel) {
        const uint4* A4 = reinterpret_cast<const uint4*>(smem) + s * 2048;
        const int   rowb  = rowc + shift;                 // 0..245
        const uint32_t addrR = sb + B_OFF + (uint32_t)bsel * B_STG
                             + (uint32_t)rowb * 128u;
        const uint32_t rsw = (uint32_t)(rowb & 7);
        #pragma unroll
        for (int ks = 0; ks < 4; ++ks) {
            uint32_t bf[4][2];
            const uint32_t goff = (((uint32_t)(2 * ks + lh)) ^ rsw) << 4;
            #pragma unroll
            for (int p = 0; p < 2; ++p)
                ldmx4(bf[p * 2][0], bf[p * 2][1],
                      bf[p * 2 + 1][0], bf[p * 2 + 1][1],
                      addrR + (uint32_t)p * 2048u + goff);
            #pragma unroll
            for (int mi = 0; mi < 4; ++mi) {
                uint4 af = A4[((wm * 4 + mi) * 4 + ks) * 32 + lane];
                uint32_t a_[4] = { af.x, af.y, af.z, af.w };
                #pragma unroll
                for (int ni = 0; ni < 4; ++ni)
                    mma_f16(acc[mi][ni], a_, bf[ni]);
            }
        }
    };

    // ---- pipeline: B0+A0 | A1 | A2 preamble, then one sync per chunk ----
    loadB(0, 0);
    prefetchA(0, 0);
    asm volatile("cp.async.commit_group;" ::: "memory");
    prefetchA(1, 1);
    asm volatile("cp.async.commit_group;" ::: "memory");
    prefetchA(2, 2);
    asm volatile("cp.async.commit_group;" ::: "memory");

    #pragma unroll 1
    for (int q = 0; q < NCHUNK; ++q) {
        asm volatile("cp.async.wait_group 2;" ::: "memory");
        __syncthreads();
        if (q + 3 < NCHUNK) prefetchA(q + 3, (q + 3) & 3);
        if (q == 5) loadB(1, 1);     // B1 ready long before q=9
        asm volatile("cp.async.commit_group;" ::: "memory");
        const int ck  = (q >= 9) ? 1 : 0;
        const int tap = q - ck * 9;
        const int shift = (tap / 3 - 1) * HP + (tap % 3 - 1);
        compute(q & 3, shift, ck);
    }

    // ---- epilogue: +bias, predicated scalar stores (skip pad columns) ----
    const int g   = lane >> 2;
    const int tig = lane & 3;
    const int co_base = wm * 64 + g;
    float bv[4][2];
    #pragma unroll
    for (int mi = 0; mi < 4; ++mi) {
        bv[mi][0] = bias[co_base + mi * 16];
        bv[mi][1] = bias[co_base + mi * 16 + 8];
    }
    #pragma unroll
    for (int ni = 0; ni < 4; ++ni) {
        const int p    = p0 + wn * 32 + ni * 8 + 2 * tig;
        const int prow = p / HP;
        const int pcol = p - prow * HP;
        const bool rv  = (prow <= 56);
        const bool v0  = rv && (pcol >= 1) && (pcol <= 56);
        const bool v1  = rv && (pcol <= 55);
        const int obase = (prow - 1) * HWD + (pcol - 1);
        float* oi = out + (size_t)img * COUT * LSP + obase;
        #pragma unroll
        for (int mi = 0; mi < 4; ++mi) {
            #pragma unroll
            for (int h = 0; h < 2; ++h) {
                const int co = co_base + mi * 16 + h * 8;
                float* op = oi + (size_t)co * LSP;
                if (v0) op[0] = acc[mi][ni][h * 2 + 0] + bv[mi][h];
                if (v1) op[1] = acc[mi][ni][h * 2 + 1] + bv[mi][h];
            }
        }
    }
}

// ---------------------------------------------------------------------------
extern "C" void kernel_launch(void* const* d_in, const int* in_sizes, int n_in,
                              void* d_out, int out_size) {
    const float* x    = (const float*)d_in[0];
    const float* w    = (const float*)d_in[1];
    const float* bias = (const float*)d_in[2];
    float* out = (float*)d_out;

    cudaFuncSetAttribute(conv_mma_kernel,
                         cudaFuncAttributeMaxDynamicSharedMemorySize, SMEMB);

    transform_kernel<<<(X4PN + WT_N + 255) / 256, 256>>>(x, w);
    conv_mma_kernel<<<NCTA, 512, SMEMB>>>(bias, out);
}